// round 16
// baseline (speedup 1.0000x reference)
#include <cuda_runtime.h>
#include <cuda_bf16.h>
#include <math.h>
#include <stdint.h>

typedef __nv_bfloat16 bf16;

#define BSZ   2
#define SEQ   2048
#define HID   4096
#define NH    32
#define DH    128
#define MROWS (BSZ * SEQ)

// ---------------- scratch (static device globals; no allocation allowed) ----
__device__ bf16 g_Xh[(size_t)MROWS * HID],  g_Xl[(size_t)MROWS * HID];
__device__ bf16 g_AOh[(size_t)MROWS * HID], g_AOl[(size_t)MROWS * HID];
__device__ bf16 g_Wqh[(size_t)HID * HID], g_Wql[(size_t)HID * HID];
__device__ bf16 g_Wkh[(size_t)HID * HID], g_Wkl[(size_t)HID * HID];
__device__ bf16 g_Wvh[(size_t)HID * HID], g_Wvl[(size_t)HID * HID];
__device__ bf16 g_Woh[(size_t)HID * HID], g_Wol[(size_t)HID * HID];
__device__ bf16 g_Qbh[(size_t)MROWS * HID], g_Qbl[(size_t)MROWS * HID];
__device__ bf16 g_Kbh[(size_t)MROWS * HID], g_Kbl[(size_t)MROWS * HID];
__device__ bf16 g_Vth[(size_t)MROWS * HID], g_Vtl[(size_t)MROWS * HID];

// ---------------- PTX helpers (all sm_80-class; no 'a'-gated features) -----
__device__ __forceinline__ uint32_t cvta_s(const void* p) {
    return (uint32_t)__cvta_generic_to_shared(p);
}
#define CP_ASYNC16(saddr, gptr) \
    asm volatile("cp.async.cg.shared.global [%0], [%1], 16;" \
                 :: "r"(saddr), "l"(gptr))
#define CP_COMMIT() asm volatile("cp.async.commit_group;")
#define CP_WAIT0()  asm volatile("cp.async.wait_group 0;")

#define LDSM4(r, addr) \
    asm volatile("ldmatrix.sync.aligned.m8n8.x4.shared.b16 {%0,%1,%2,%3}, [%4];" \
                 : "=r"((r)[0]), "=r"((r)[1]), "=r"((r)[2]), "=r"((r)[3]) \
                 : "r"(addr))

#define MMA16816(d, a, b) \
    asm volatile("mma.sync.aligned.m16n8k16.row.col.f32.bf16.bf16.f32 " \
                 "{%0,%1,%2,%3}, {%4,%5,%6,%7}, {%8,%9}, {%0,%1,%2,%3};" \
                 : "+f"((d)[0]), "+f"((d)[1]), "+f"((d)[2]), "+f"((d)[3]) \
                 : "r"((a)[0]), "r"((a)[1]), "r"((a)[2]), "r"((a)[3]), \
                   "r"((b)[0]), "r"((b)[1]))

__device__ __forceinline__ void split_hl(float a, bf16& h, bf16& l) {
    h = __float2bfloat16(a);
    l = __float2bfloat16(a - __bfloat162float(h));
}
__device__ __forceinline__ void pack_hl(float a, float b,
                                        uint32_t& hi, uint32_t& lo) {
    bf16 ha, la, hb, lb;
    split_hl(a, ha, la);
    split_hl(b, hb, lb);
    __nv_bfloat162 hp; hp.x = ha; hp.y = hb;
    __nv_bfloat162 lp; lp.x = la; lp.y = lb;
    hi = *(uint32_t*)&hp;
    lo = *(uint32_t*)&lp;
}

// =========================================================================
// split-to-bf16 conversion. dst_sel: 0=X 1=Wq 2=Wk 3=Wv 4=Wo
// =========================================================================
__global__ __launch_bounds__(256) void convert_split(const float* __restrict__ src,
                                                     int dst_sel) {
    bf16 *hi, *lo;
    switch (dst_sel) {
        case 1: hi = g_Wqh; lo = g_Wql; break;
        case 2: hi = g_Wkh; lo = g_Wkl; break;
        case 3: hi = g_Wvh; lo = g_Wvl; break;
        case 4: hi = g_Woh; lo = g_Wol; break;
        default: hi = g_Xh;  lo = g_Xl;  break;
    }
    size_t i = (size_t)blockIdx.x * blockDim.x + threadIdx.x;
    float4 v = ((const float4*)src)[i];
    uint32_t h0, l0, h1, l1;
    pack_hl(v.x, v.y, h0, l0);
    pack_hl(v.z, v.w, h1, l1);
    ((uint32_t*)hi)[i * 2]     = h0;
    ((uint32_t*)hi)[i * 2 + 1] = h1;
    ((uint32_t*)lo)[i * 2]     = l0;
    ((uint32_t*)lo)[i * 2 + 1] = l1;
}

// =========================================================================
// mma.sync bf16 3-term GEMM, CTA tile 128x256, 8 warps of 64x64.
// Buffer layout: Ah[16K] Al[16K] Bh[32K] Bl[32K] = 96KB, double buffered.
// mode 0: X @ W{q,k,v}; fused epilogue (rope+split / V-transpose+split).
// mode 1: AO @ Wo -> fp32 Cext.
// =========================================================================
#define A_TILE   16384
#define B_TILE   32768
#define OFF_AH   0
#define OFF_AL   16384
#define OFF_BH   32768
#define OFF_BL   65536
#define BUF_B    98304
#define GEMM_SMEM (2 * BUF_B)
#define NCHUNK   64
#define FST      257      // fp32 staging stride

__global__ __launch_bounds__(256, 1) void gemm_mma3(float* __restrict__ Cext,
                                                    int mode,
                                                    const int* __restrict__ pos) {
    extern __shared__ char dsm[];
    const uint32_t sb = cvta_s(dsm);
    __shared__ float s_inv[64];

    const int z = blockIdx.z;
    const bf16 *Ah, *Al, *Wh, *Wl;
    if (mode == 0) {
        Ah = g_Xh; Al = g_Xl;
        Wh = (z == 0) ? g_Wqh : (z == 1) ? g_Wkh : g_Wvh;
        Wl = (z == 0) ? g_Wql : (z == 1) ? g_Wkl : g_Wvl;
        if (z < 2 && threadIdx.x < 64)
            s_inv[threadIdx.x] =
                (float)exp(-(double)threadIdx.x * (2.0 / (double)DH) * log(10000.0));
    } else {
        Ah = g_AOh; Al = g_AOl; Wh = g_Woh; Wl = g_Wol;
    }

    const int t    = threadIdx.x;
    const int lane = t & 31;
    const int wid  = t >> 5;
    const int wm   = wid >> 2;          // 0..1 -> m offset wm*64
    const int wn   = wid & 3;           // 0..3 -> n offset wn*64
    const int bm   = blockIdx.y * 128;
    const int bn   = blockIdx.x * 256;

    const int lxor = lane & 7;
    uint32_t aRow[4], bRow[4];
#pragma unroll
    for (int mt = 0; mt < 4; ++mt)
        aRow[mt] = (uint32_t)((wm * 64 + mt * 16 + (lane & 15)) * 128);
#pragma unroll
    for (int np = 0; np < 4; ++np)
        bRow[np] = (uint32_t)((wn * 64 + np * 16 + (lane & 7) + ((lane & 16) >> 1)) * 128);
    const int uA = lane >> 4;
    const int uB = (lane >> 3) & 1;

    auto load_chunk = [&](int buf, int k0) {
        const uint32_t bb = sb + buf * BUF_B;
        // A tiles: 128 rows x 64 k, both splits
#pragma unroll
        for (int i = 0; i < 4; ++i) {
            int idx = t + i * 256;          // 0..1023
            int r = idx >> 3, u = idx & 7;
            uint32_t so = (uint32_t)(r * 128 + ((u ^ (r & 7)) << 4));
            size_t go = (size_t)(bm + r) * HID + k0 + u * 8;
            CP_ASYNC16(bb + OFF_AH + so, Ah + go);
            CP_ASYNC16(bb + OFF_AL + so, Al + go);
        }
        // B tiles: 256 rows x 64 k, both splits
#pragma unroll
        for (int i = 0; i < 8; ++i) {
            int idx = t + i * 256;          // 0..2047
            int r = idx >> 3, u = idx & 7;
            uint32_t so = (uint32_t)(r * 128 + ((u ^ (r & 7)) << 4));
            size_t go = (size_t)(bn + r) * HID + k0 + u * 8;
            CP_ASYNC16(bb + OFF_BH + so, Wh + go);
            CP_ASYNC16(bb + OFF_BL + so, Wl + go);
        }
    };

    float acc[4][8][4];
#pragma unroll
    for (int mt = 0; mt < 4; ++mt)
#pragma unroll
        for (int nt = 0; nt < 8; ++nt)
#pragma unroll
            for (int j = 0; j < 4; ++j) acc[mt][nt][j] = 0.0f;

    load_chunk(0, 0);
    CP_COMMIT();
    CP_WAIT0();
    __syncthreads();

    for (int c = 0; c < NCHUNK; ++c) {
        const int buf = c & 1;
        if (c + 1 < NCHUNK) {
            load_chunk(buf ^ 1, (c + 1) * 64);
            CP_COMMIT();
        }

        const uint32_t base = sb + buf * BUF_B;
#pragma unroll
        for (int ks = 0; ks < 4; ++ks) {
            const uint32_t offA = (uint32_t)((((2 * ks + uA) ^ lxor)) << 4);
            const uint32_t offB = (uint32_t)((((2 * ks + uB) ^ lxor)) << 4);
            uint32_t aH[4][4], aL[4][4];
#pragma unroll
            for (int mt = 0; mt < 4; ++mt) {
                LDSM4(aH[mt], base + OFF_AH + aRow[mt] + offA);
                LDSM4(aL[mt], base + OFF_AL + aRow[mt] + offA);
            }
#pragma unroll
            for (int np = 0; np < 4; ++np) {
                uint32_t bH[4], bL[4];
                LDSM4(bH, base + OFF_BH + bRow[np] + offB);
                LDSM4(bL, base + OFF_BL + bRow[np] + offB);
#pragma unroll
                for (int mt = 0; mt < 4; ++mt)
#pragma unroll
                    for (int half = 0; half < 2; ++half) {
                        float* ap = acc[mt][np * 2 + half];
                        MMA16816(ap, aH[mt], &bH[half * 2]);
                        MMA16816(ap, aH[mt], &bL[half * 2]);
                        MMA16816(ap, aL[mt], &bH[half * 2]);
                    }
            }
        }

        if (c + 1 < NCHUNK) {
            CP_WAIT0();
            __syncthreads();
        }
    }

    const int g  = lane >> 2;
    const int tq = lane & 3;

    if (mode == 1) {
#pragma unroll
        for (int mt = 0; mt < 4; ++mt) {
            const int row0 = bm + wm * 64 + mt * 16 + g;
#pragma unroll
            for (int nt = 0; nt < 8; ++nt) {
                const int col = bn + wn * 64 + nt * 8 + tq * 2;
                *(float2*)(Cext + (size_t)row0 * HID + col) =
                    make_float2(acc[mt][nt][0], acc[mt][nt][1]);
                *(float2*)(Cext + (size_t)(row0 + 8) * HID + col) =
                    make_float2(acc[mt][nt][2], acc[mt][nt][3]);
            }
        }
        return;
    }

    // ---- fused epilogue: stage fp32 tile (128 x 256) to smem ----
    __syncthreads();
    float* fsm = (float*)dsm;
#pragma unroll
    for (int mt = 0; mt < 4; ++mt) {
        const int r0 = wm * 64 + mt * 16 + g;
#pragma unroll
        for (int nt = 0; nt < 8; ++nt) {
            const int cc = wn * 64 + nt * 8 + tq * 2;
            fsm[r0 * FST + cc]           = acc[mt][nt][0];
            fsm[r0 * FST + cc + 1]       = acc[mt][nt][1];
            fsm[(r0 + 8) * FST + cc]     = acc[mt][nt][2];
            fsm[(r0 + 8) * FST + cc + 1] = acc[mt][nt][3];
        }
    }
    __syncthreads();

    if (z < 2) {
        // ---- RoPE + scale + split (2 heads per tile) ----
        const bool isQ = (z == 0);
        const float sc = isQ ? 0.08838834764831845f : 1.0f;
        bf16* hi = isQ ? g_Qbh : g_Kbh;
        bf16* lo = isQ ? g_Qbl : g_Kbl;
#pragma unroll
        for (int it = 0; it < 64; ++it) {
            int pi = t + it * 256;           // 0..16383
            int r  = pi >> 7;                // 0..127
            int p2 = pi & 127;               // pair index: head_l*64 + j
            int hl = p2 >> 6;
            int j  = p2 & 63;
            int c1 = hl * 128 + j;
            float x1 = fsm[r * FST + c1];
            float x2 = fsm[r * FST + c1 + 64];
            int s = (bm + r) & (SEQ - 1);
            float p = (float)pos[s];
            float sn, cs;
            sincosf(p * s_inv[j], &sn, &cs);
            float y1 = (x1 * cs - x2 * sn) * sc;
            float y2 = (x2 * cs + x1 * sn) * sc;
            bf16 h1, l1, h2, l2;
            split_hl(y1, h1, l1);
            split_hl(y2, h2, l2);
            size_t o = (size_t)(bm + r) * HID + bn + c1;
            hi[o] = h1;       lo[o] = l1;
            hi[o + 64] = h2;  lo[o + 64] = l2;
        }
    } else {
        // ---- V: transpose + split -> [b,h,d,s] (2 heads per tile) ----
        const int bb2 = bm >> 11;            // batch (SEQ = 2048)
        const int sbase = bm & (SEQ - 1);
        const int h0 = bn >> 7;
#pragma unroll
        for (int it = 0; it < 64; ++it) {
            int idx = t + it * 256;          // 0..16383
            int dc = idx >> 6;               // 0..255
            int s2 = (idx & 63) * 2;
            int hh = h0 + (dc >> 7);
            int d  = dc & 127;
            float v0 = fsm[s2 * FST + dc];
            float v1 = fsm[(s2 + 1) * FST + dc];
            uint32_t hv, lv;
            pack_hl(v0, v1, hv, lv);
            size_t o = ((size_t)((bb2 * NH + hh) * DH + d)) * SEQ + sbase + s2;
            *(uint32_t*)(g_Vth + o) = hv;
            *(uint32_t*)(g_Vtl + o) = lv;
        }
    }
}

// =========================================================================
// Causal flash attention on mma.sync bf16x3 (unchanged from round-12 pass).
// =========================================================================
#define ATQ_B  32768
#define KV_B   65536
#define ATTN_SMEM (2 * ATQ_B + 2 * KV_B)

__global__ __launch_bounds__(256, 1) void flash_attn_mma()
{
    extern __shared__ char sm[];
    const uint32_t sb = cvta_s(sm);
    const int qt = blockIdx.x, h = blockIdx.y, b = blockIdx.z;
    const int qbase = qt * 128;
    const int t = threadIdx.x, lane = t & 31, w = t >> 5;

    {
        const bf16* srcs[2] = {g_Qbh, g_Qbl};
#pragma unroll
        for (int sp = 0; sp < 2; ++sp) {
            const bf16* src = srcs[sp];
#pragma unroll
            for (int i = 0; i < 8; ++i) {
                int idx = t + i * 256;
                int r = idx >> 4, u = idx & 15;
                uint32_t sw = (uint32_t)(((u & 7) ^ (r & 7)) | (u & 8));
                const bf16* g = src + (size_t)(b * SEQ + qbase + r) * HID
                                    + h * DH + u * 8;
                CP_ASYNC16(sb + sp * ATQ_B + r * 256 + (sw << 4), g);
            }
        }
    }

    auto load_kv = [&](int buf, int kt) {
        const uint32_t off = 2 * ATQ_B + buf * KV_B;
        const int kbase = kt * 64;
#pragma unroll
        for (int i = 0; i < 4; ++i) {
            int idx = t + i * 256;
            int r = idx >> 4, u = idx & 15;
            uint32_t sw = (uint32_t)(((u & 7) ^ (r & 7)) | (u & 8));
            size_t gi = (size_t)(b * SEQ + kbase + r) * HID + h * DH + u * 8;
            CP_ASYNC16(sb + off + r * 256 + (sw << 4), g_Kbh + gi);
            CP_ASYNC16(sb + off + 16384 + r * 256 + (sw << 4), g_Kbl + gi);
        }
#pragma unroll
        for (int i = 0; i < 4; ++i) {
            int idx = t + i * 256;
            int d = idx >> 3, u = idx & 7;
            uint32_t sw = (uint32_t)(u ^ (d & 7));
            size_t gi = (size_t)((b * NH + h) * DH + d) * SEQ + kbase + u * 8;
            CP_ASYNC16(sb + off + 32768 + d * 128 + (sw << 4), g_Vth + gi);
            CP_ASYNC16(sb + off + 49152 + d * 128 + (sw << 4), g_Vtl + gi);
        }
    };

    load_kv(0, 0);
    CP_COMMIT();
    CP_WAIT0();
    __syncthreads();

    float of[16][4];
#pragma unroll
    for (int nt = 0; nt < 16; ++nt)
#pragma unroll
        for (int j = 0; j < 4; ++j) of[nt][j] = 0.0f;
    float m0 = -1e30f, m1 = -1e30f, l0 = 0.0f, l1 = 0.0f;

    const int nkt = 2 * (qt + 1);
    for (int kt = 0; kt < nkt; ++kt) {
        const int buf = kt & 1;
        if (kt + 1 < nkt) {
            load_kv(buf ^ 1, kt + 1);
            CP_COMMIT();
        }
        const uint32_t kb = sb + 2 * ATQ_B + buf * KV_B;

        float s[8][4];
#pragma unroll
        for (int nt = 0; nt < 8; ++nt)
#pragma unroll
            for (int j = 0; j < 4; ++j) s[nt][j] = 0.0f;

#pragma unroll
        for (int ks = 0; ks < 8; ++ks) {
            uint32_t aH[4], aL[4];
            {
                int r = w * 16 + (lane & 15);
                int c = 2 * ks + (lane >> 4);
                uint32_t sw = (uint32_t)(((c & 7) ^ (r & 7)) | (c & 8));
                uint32_t ad = sb + r * 256 + (sw << 4);
                LDSM4(aH, ad);
                LDSM4(aL, ad + ATQ_B);
            }
#pragma unroll
            for (int np = 0; np < 4; ++np) {
                uint32_t bH[4], bL[4];
                int rr = np * 16 + (lane & 7) + ((lane >> 4) << 3);
                int c  = 2 * ks + ((lane >> 3) & 1);
                uint32_t sw = (uint32_t)(((c & 7) ^ (rr & 7)) | (c & 8));
                uint32_t ad = kb + rr * 256 + (sw << 4);
                LDSM4(bH, ad);
                LDSM4(bL, ad + 16384);
#pragma unroll
                for (int half = 0; half < 2; ++half) {
                    float* acc = s[np * 2 + half];
                    MMA16816(acc, aH, &bH[half * 2]);
                    MMA16816(acc, aH, &bL[half * 2]);
                    MMA16816(acc, aL, &bH[half * 2]);
                }
            }
        }

        const int kbase = kt * 64;
        const int r1g = qbase + w * 16 + (lane >> 2);
        if (kbase + 63 > r1g) {
            const int r2g = r1g + 8;
#pragma unroll
            for (int nt = 0; nt < 8; ++nt) {
                int cg = kbase + nt * 8 + 2 * (lane & 3);
                if (cg > r1g)     s[nt][0] = -1e30f;
                if (cg + 1 > r1g) s[nt][1] = -1e30f;
                if (cg > r2g)     s[nt][2] = -1e30f;
                if (cg + 1 > r2g) s[nt][3] = -1e30f;
            }
        }

        float mi0 = -1e30f, mi1 = -1e30f;
#pragma unroll
        for (int nt = 0; nt < 8; ++nt) {
            mi0 = fmaxf(mi0, fmaxf(s[nt][0], s[nt][1]));
            mi1 = fmaxf(mi1, fmaxf(s[nt][2], s[nt][3]));
        }
        mi0 = fmaxf(mi0, __shfl_xor_sync(0xffffffffu, mi0, 1));
        mi0 = fmaxf(mi0, __shfl_xor_sync(0xffffffffu, mi0, 2));
        mi1 = fmaxf(mi1, __shfl_xor_sync(0xffffffffu, mi1, 1));
        mi1 = fmaxf(mi1, __shfl_xor_sync(0xffffffffu, mi1, 2));
        const float mn0 = fmaxf(m0, mi0), mn1 = fmaxf(m1, mi1);
        const float al0 = __expf(m0 - mn0), al1 = __expf(m1 - mn1);
        float rs0 = 0.0f, rs1 = 0.0f;
#pragma unroll
        for (int nt = 0; nt < 8; ++nt) {
            s[nt][0] = __expf(s[nt][0] - mn0);
            s[nt][1] = __expf(s[nt][1] - mn0);
            s[nt][2] = __expf(s[nt][2] - mn1);
            s[nt][3] = __expf(s[nt][3] - mn1);
            rs0 += s[nt][0] + s[nt][1];
            rs1 += s[nt][2] + s[nt][3];
        }
        rs0 += __shfl_xor_sync(0xffffffffu, rs0, 1);
        rs0 += __shfl_xor_sync(0xffffffffu, rs0, 2);
        rs1 += __shfl_xor_sync(0xffffffffu, rs1, 1);
        rs1 += __shfl_xor_sync(0xffffffffu, rs1, 2);
        l0 = l0 * al0 + rs0;
        l1 = l1 * al1 + rs1;
        m0 = mn0; m1 = mn1;
#pragma unroll
        for (int nt = 0; nt < 16; ++nt) {
            of[nt][0] *= al0; of[nt][1] *= al0;
            of[nt][2] *= al1; of[nt][3] *= al1;
        }

#pragma unroll
        for (int kc = 0; kc < 4; ++kc) {
            uint32_t pH[4], pL[4];
            pack_hl(s[2 * kc][0],     s[2 * kc][1],     pH[0], pL[0]);
            pack_hl(s[2 * kc][2],     s[2 * kc][3],     pH[1], pL[1]);
            pack_hl(s[2 * kc + 1][0], s[2 * kc + 1][1], pH[2], pL[2]);
            pack_hl(s[2 * kc + 1][2], s[2 * kc + 1][3], pH[3], pL[3]);
#pragma unroll
            for (int np = 0; np < 8; ++np) {
                uint32_t vH[4], vL[4];
                int dd = np * 16 + (lane & 7) + ((lane >> 4) << 3);
                int c  = 2 * kc + ((lane >> 3) & 1);
                uint32_t sw = (uint32_t)(c ^ (dd & 7));
                uint32_t ad = kb + 32768 + dd * 128 + (sw << 4);
                LDSM4(vH, ad);
                LDSM4(vL, ad + 16384);
#pragma unroll
                for (int half = 0; half < 2; ++half) {
                    float* acc = of[np * 2 + half];
                    MMA16816(acc, pH, &vH[half * 2]);
                    MMA16816(acc, pH, &vL[half * 2]);
                    MMA16816(acc, pL, &vH[half * 2]);
                }
            }
        }

        if (kt + 1 < nkt) {
            CP_WAIT0();
            __syncthreads();
        }
    }

    const float inv0 = 1.0f / l0, inv1 = 1.0f / l1;
    const int r1 = qbase + w * 16 + (lane >> 2);
#pragma unroll
    for (int nt = 0; nt < 16; ++nt) {
        const int d = h * DH + nt * 8 + 2 * (lane & 3);
        const size_t o1 = (size_t)(b * SEQ + r1) * HID + d;
        const size_t o2 = (size_t)(b * SEQ + r1 + 8) * HID + d;
        uint32_t hv, lv;
        pack_hl(of[nt][0] * inv0, of[nt][1] * inv0, hv, lv);
        *(uint32_t*)(g_AOh + o1) = hv;
        *(uint32_t*)(g_AOl + o1) = lv;
        pack_hl(of[nt][2] * inv1, of[nt][3] * inv1, hv, lv);
        *(uint32_t*)(g_AOh + o2) = hv;
        *(uint32_t*)(g_AOl + o2) = lv;
    }
}

// =========================================================================
extern "C" void kernel_launch(void* const* d_in, const int* in_sizes, int n_in,
                              void* d_out, int out_size)
{
    const float* X  = (const float*)d_in[0];
    const float* Wq = (const float*)d_in[1];
    const float* Wk = (const float*)d_in[2];
    const float* Wv = (const float*)d_in[3];
    const float* Wo = (const float*)d_in[4];
    const int*  pos = (const int*)d_in[6];
    float* out = (float*)d_out;

    const int conv_blocks = (int)(((size_t)HID * HID / 4) / 256);   // 16384

    convert_split<<<conv_blocks, 256>>>(X,  0);
    convert_split<<<conv_blocks, 256>>>(Wq, 1);
    convert_split<<<conv_blocks, 256>>>(Wk, 2);
    convert_split<<<conv_blocks, 256>>>(Wv, 3);
    convert_split<<<conv_blocks, 256>>>(Wo, 4);

    cudaFuncSetAttribute(gemm_mma3,
                         cudaFuncAttributeMaxDynamicSharedMemorySize, GEMM_SMEM);
    gemm_mma3<<<dim3(HID / 256, MROWS / 128, 3), 256, GEMM_SMEM>>>(nullptr, 0, pos);

    cudaFuncSetAttribute(flash_attn_mma,
                         cudaFuncAttributeMaxDynamicSharedMemorySize, ATTN_SMEM);
    flash_attn_mma<<<dim3(SEQ / 128, NH, BSZ), 256, ATTN_SMEM>>>();

    gemm_mma3<<<dim3(HID / 256, MROWS / 128, 1), 256, GEMM_SMEM>>>(out, 1, pos);
}